// round 1
// baseline (speedup 1.0000x reference)
#include <cuda_runtime.h>
#include <cstdint>
#include <math.h>

#define L_  8
#define D_  1024
#define H_  16
#define DH_ 64
#define DI_ 4096
#define V_  32000
#define B_  2
#define S_  1024
#define T_  (B_*S_)

// ---------------- scratch (static device arrays; no allocation) ----------------
__device__ float g_h   [T_*D_];
__device__ float g_hn  [T_*D_];
__device__ float g_q   [T_*D_];
__device__ float g_k   [T_*D_];
__device__ float g_v   [T_*D_];
__device__ float g_y   [T_*D_];
__device__ float g_gate[T_*DI_];
__device__ float g_up  [T_*DI_];
__device__ float g_att [(size_t)B_*H_*S_*S_];
__device__ float g_cos [S_*32];
__device__ float g_sin [S_*32];

// ---------------- small kernels ----------------
__global__ void embed_kernel(const int* __restrict__ x, const float* __restrict__ emb,
                             float* __restrict__ h) {
    int i = blockIdx.x * blockDim.x + threadIdx.x;       // over T_*D_/4
    int t = i / (D_/4);
    int c = i % (D_/4);
    float4 v = *(const float4*)(emb + (size_t)x[t]*D_ + c*4);
    *(float4*)(h + (size_t)t*D_ + c*4) = v;
}

__global__ void rope_cache_kernel() {
    int i = blockIdx.x * blockDim.x + threadIdx.x;       // S_*32
    if (i >= S_*32) return;
    int s = i / 32, j = i % 32;
    double inv = pow(10000.0, -(double)j / 32.0);
    double ph = (double)s * inv;
    g_cos[i] = (float)cos(ph);
    g_sin[i] = (float)sin(ph);
}

__global__ void rope_kernel(float* __restrict__ q, float* __restrict__ k) {
    int i = blockIdx.x * blockDim.x + threadIdx.x;       // T_*H_*32
    int t = i >> 9;          // / (H_*32)
    int r = i & 511;
    int h = r >> 5, d = r & 31;
    int s = t & (S_-1);
    float c  = g_cos[s*32 + d];
    float sn = g_sin[s*32 + d];
    size_t base = (size_t)t*D_ + h*DH_ + d;
    float a, b;
    a = q[base]; b = q[base+32];
    q[base]    = a*c - b*sn;
    q[base+32] = b*c + a*sn;
    a = k[base]; b = k[base+32];
    k[base]    = a*c - b*sn;
    k[base+32] = b*c + a*sn;
}

__global__ void rmsnorm_kernel(const float* __restrict__ x, const float* __restrict__ w,
                               float* __restrict__ o) {
    int t = blockIdx.x;
    int tid = threadIdx.x;
    const float* xp = x + (size_t)t*D_;
    float v[4];
    float s = 0.f;
    #pragma unroll
    for (int i = 0; i < 4; i++) { v[i] = xp[tid + i*256]; s += v[i]*v[i]; }
    #pragma unroll
    for (int off = 16; off; off >>= 1) s += __shfl_xor_sync(0xffffffffu, s, off);
    __shared__ float red[8];
    if ((tid & 31) == 0) red[tid >> 5] = s;
    __syncthreads();
    if (tid < 32) {
        float s2 = (tid < 8) ? red[tid] : 0.f;
        #pragma unroll
        for (int off = 4; off; off >>= 1) s2 += __shfl_xor_sync(0xffffffffu, s2, off);
        if (tid == 0) red[0] = s2;
    }
    __syncthreads();
    float r = rsqrtf(red[0] * (1.f/(float)D_) + 1e-6f);
    float* op = o + (size_t)t*D_;
    #pragma unroll
    for (int i = 0; i < 4; i++) op[tid + i*256] = w[tid + i*256] * v[i] * r;
}

__global__ void softmax_kernel(float* __restrict__ att) {
    float* p = att + (size_t)blockIdx.x * S_;
    int tid = threadIdx.x;
    float vals[4];
    float mx = -INFINITY;
    #pragma unroll
    for (int i = 0; i < 4; i++) { vals[i] = p[tid + i*256]; mx = fmaxf(mx, vals[i]); }
    #pragma unroll
    for (int off = 16; off; off >>= 1) mx = fmaxf(mx, __shfl_xor_sync(0xffffffffu, mx, off));
    __shared__ float redm[8];
    if ((tid & 31) == 0) redm[tid >> 5] = mx;
    __syncthreads();
    if (tid < 32) {
        float m2 = (tid < 8) ? redm[tid] : -INFINITY;
        #pragma unroll
        for (int off = 4; off; off >>= 1) m2 = fmaxf(m2, __shfl_xor_sync(0xffffffffu, m2, off));
        if (tid == 0) redm[0] = m2;
    }
    __syncthreads();
    float m = redm[0];
    float s = 0.f;
    #pragma unroll
    for (int i = 0; i < 4; i++) { vals[i] = expf(vals[i] - m); s += vals[i]; }
    #pragma unroll
    for (int off = 16; off; off >>= 1) s += __shfl_xor_sync(0xffffffffu, s, off);
    __shared__ float reds[8];
    if ((tid & 31) == 0) reds[tid >> 5] = s;
    __syncthreads();
    if (tid < 32) {
        float s2 = (tid < 8) ? reds[tid] : 0.f;
        #pragma unroll
        for (int off = 4; off; off >>= 1) s2 += __shfl_xor_sync(0xffffffffu, s2, off);
        if (tid == 0) reds[0] = s2;
    }
    __syncthreads();
    float inv = 1.f / reds[0];
    #pragma unroll
    for (int i = 0; i < 4; i++) p[tid + i*256] = vals[i] * inv;
}

__global__ void silu_mul_kernel(float* __restrict__ g, const float* __restrict__ u) {
    int i = blockIdx.x * blockDim.x + threadIdx.x;       // T_*DI_
    float x = g[i];
    float sg = 1.f / (1.f + expf(-x));
    g[i] = x * sg * u[i];
}

// ---------------- generic tiled fp32 GEMM ----------------
// C[M,N] = A[M,K] @ op(B) (+ epilogue).  BT=true: B is [N,K] row-major (NT gemm).
// BT=false: B is [K,N] row-major (NN gemm).
enum { EPI_NONE = 0, EPI_BIAS = 1, EPI_BIAS_RES = 2, EPI_RES = 3, EPI_SCORES = 4 };

template<int BM, int BN, int BK, int TM, int TN, bool BT, int EPI>
__global__ __launch_bounds__((BM/TM)*(BN/TN))
void gemm_kernel(const float* __restrict__ A, const float* __restrict__ Bm,
                 float* __restrict__ C, const float* __restrict__ bias,
                 int M, int N, int K, int lda, int ldb, int ldc,
                 int zinner,
                 long long sAo, long long sAi,
                 long long sBo, long long sBi,
                 long long sCo, long long sCi,
                 float scale)
{
    constexpr int THREADS = (BM/TM)*(BN/TN);
    const int tid = threadIdx.x;
    const int z  = blockIdx.z;
    const int zo = z / zinner, zi = z % zinner;
    const float* Ab = A  + zo*sAo + zi*sAi;
    const float* Bb = Bm + zo*sBo + zi*sBi;
    float*       Cb = C  + zo*sCo + zi*sCi;
    const int m0 = blockIdx.y * BM;
    const int n0 = blockIdx.x * BN;

    __shared__ float As[BK][BM+4];
    __shared__ float Bs[BK][BN+4];

    float acc[TM][TN];
    #pragma unroll
    for (int i = 0; i < TM; i++)
        #pragma unroll
        for (int j = 0; j < TN; j++) acc[i][j] = 0.f;

    const int tx = tid % (BN/TN);
    const int ty = tid / (BN/TN);

    for (int kt = 0; kt < K; kt += BK) {
        // load A tile, transposed into As[k][m]
        #pragma unroll
        for (int i = 0; i < (BM*BK/4)/THREADS; i++) {
            int f  = tid + i*THREADS;
            int r  = f / (BK/4);
            int c4 = f % (BK/4);
            float4 v = *(const float4*)(Ab + (size_t)(m0+r)*lda + kt + c4*4);
            As[c4*4+0][r] = v.x; As[c4*4+1][r] = v.y;
            As[c4*4+2][r] = v.z; As[c4*4+3][r] = v.w;
        }
        if (BT) {
            #pragma unroll
            for (int i = 0; i < (BN*BK/4)/THREADS; i++) {
                int f  = tid + i*THREADS;
                int r  = f / (BK/4);
                int c4 = f % (BK/4);
                float4 v = *(const float4*)(Bb + (size_t)(n0+r)*ldb + kt + c4*4);
                Bs[c4*4+0][r] = v.x; Bs[c4*4+1][r] = v.y;
                Bs[c4*4+2][r] = v.z; Bs[c4*4+3][r] = v.w;
            }
        } else {
            #pragma unroll
            for (int i = 0; i < (BK*BN/4)/THREADS; i++) {
                int f  = tid + i*THREADS;
                int r  = f / (BN/4);
                int c4 = f % (BN/4);
                float4 v = *(const float4*)(Bb + (size_t)(kt+r)*ldb + n0 + c4*4);
                *(float4*)(&Bs[r][c4*4]) = v;
            }
        }
        __syncthreads();
        #pragma unroll
        for (int k = 0; k < BK; k++) {
            float ar[TM], br[TN];
            #pragma unroll
            for (int i = 0; i < TM; i++) ar[i] = As[k][ty*TM + i];
            #pragma unroll
            for (int j = 0; j < TN; j++) br[j] = Bs[k][tx*TN + j];
            #pragma unroll
            for (int i = 0; i < TM; i++)
                #pragma unroll
                for (int j = 0; j < TN; j++) acc[i][j] += ar[i]*br[j];
        }
        __syncthreads();
    }

    #pragma unroll
    for (int i = 0; i < TM; i++) {
        int m = m0 + ty*TM + i;
        #pragma unroll
        for (int j = 0; j < TN; j++) {
            int n = n0 + tx*TN + j;
            size_t off = (size_t)m*ldc + n;
            float v = acc[i][j];
            if (EPI == EPI_BIAS)      v += bias[n];
            else if (EPI == EPI_BIAS_RES) v += bias[n] + Cb[off];
            else if (EPI == EPI_RES)  v += Cb[off];
            else if (EPI == EPI_SCORES) v = (n <= m) ? v*scale : -INFINITY;
            Cb[off] = v;
        }
    }
}

// ---------------- host ----------------
extern "C" void kernel_launch(void* const* d_in, const int* in_sizes, int n_in,
                              void* d_out, int out_size) {
    const int*   x      = (const int*)  d_in[0];
    const float* emb    = (const float*)d_in[1];
    const float* wq     = (const float*)d_in[2];
    const float* bq     = (const float*)d_in[3];
    const float* wk     = (const float*)d_in[4];
    const float* bk     = (const float*)d_in[5];
    const float* wv     = (const float*)d_in[6];
    const float* bv     = (const float*)d_in[7];
    const float* wo     = (const float*)d_in[8];
    const float* bo     = (const float*)d_in[9];
    const float* w_gate = (const float*)d_in[10];
    const float* w_up   = (const float*)d_in[11];
    const float* w_down = (const float*)d_in[12];
    const float* ln1    = (const float*)d_in[13];
    const float* ln2    = (const float*)d_in[14];
    const float* norm_w = (const float*)d_in[15];
    float* out = (float*)d_out;

    float *h, *hn, *q, *k, *v, *y, *gate, *up, *att;
    cudaGetSymbolAddress((void**)&h,    g_h);
    cudaGetSymbolAddress((void**)&hn,   g_hn);
    cudaGetSymbolAddress((void**)&q,    g_q);
    cudaGetSymbolAddress((void**)&k,    g_k);
    cudaGetSymbolAddress((void**)&v,    g_v);
    cudaGetSymbolAddress((void**)&y,    g_y);
    cudaGetSymbolAddress((void**)&gate, g_gate);
    cudaGetSymbolAddress((void**)&up,   g_up);
    cudaGetSymbolAddress((void**)&att,  g_att);

    embed_kernel<<<T_*D_/4/256, 256>>>(x, emb, h);
    rope_cache_kernel<<<(S_*32 + 255)/256, 256>>>();

    const dim3 gp(D_/64,  T_/128, 1);      // 128x64 tiles, D output
    const dim3 gm(DI_/128, T_/128, 1);     // 128x128 tiles, DI output
    const dim3 gs(S_/128, S_/128, B_*H_);  // scores
    const dim3 ga(1,      S_/128, B_*H_);  // attn*V

    for (int l = 0; l < L_; l++) {
        rmsnorm_kernel<<<T_, 256>>>(h, ln1 + (size_t)l*D_, hn);

        gemm_kernel<128,64,16,8,4,true,EPI_BIAS><<<gp,256>>>(
            hn, wq + (size_t)l*D_*D_, q, bq + (size_t)l*D_,
            T_, D_, D_, D_, D_, D_, 1, 0,0,0,0,0,0, 0.f);
        gemm_kernel<128,64,16,8,4,true,EPI_BIAS><<<gp,256>>>(
            hn, wk + (size_t)l*D_*D_, k, bk + (size_t)l*D_,
            T_, D_, D_, D_, D_, D_, 1, 0,0,0,0,0,0, 0.f);
        gemm_kernel<128,64,16,8,4,true,EPI_BIAS><<<gp,256>>>(
            hn, wv + (size_t)l*D_*D_, v, bv + (size_t)l*D_,
            T_, D_, D_, D_, D_, D_, 1, 0,0,0,0,0,0, 0.f);

        rope_kernel<<<T_*H_*32/256, 256>>>(q, k);

        // scores: per (b,h) q[S,64] @ k[S,64]^T, causal mask + scale
        gemm_kernel<128,128,16,8,8,true,EPI_SCORES><<<gs,256>>>(
            q, k, att, nullptr,
            S_, S_, DH_, D_, D_, S_,
            H_,
            (long long)S_*D_, (long long)DH_,
            (long long)S_*D_, (long long)DH_,
            (long long)H_*S_*S_, (long long)S_*S_,
            0.125f);

        softmax_kernel<<<B_*H_*S_, 256>>>(att);

        // y = att @ v  (NN gemm, N=64)
        gemm_kernel<128,64,16,8,4,false,EPI_NONE><<<ga,256>>>(
            att, v, y, nullptr,
            S_, DH_, S_, S_, D_, D_,
            H_,
            (long long)H_*S_*S_, (long long)S_*S_,
            (long long)S_*D_, (long long)DH_,
            (long long)S_*D_, (long long)DH_,
            0.f);

        gemm_kernel<128,64,16,8,4,true,EPI_BIAS_RES><<<gp,256>>>(
            y, wo + (size_t)l*D_*D_, h, bo + (size_t)l*D_,
            T_, D_, D_, D_, D_, D_, 1, 0,0,0,0,0,0, 0.f);

        rmsnorm_kernel<<<T_, 256>>>(h, ln2 + (size_t)l*D_, hn);

        gemm_kernel<128,128,16,8,8,true,EPI_NONE><<<gm,256>>>(
            hn, w_gate + (size_t)l*DI_*D_, gate, nullptr,
            T_, DI_, D_, D_, D_, DI_, 1, 0,0,0,0,0,0, 0.f);
        gemm_kernel<128,128,16,8,8,true,EPI_NONE><<<gm,256>>>(
            hn, w_up + (size_t)l*DI_*D_, up, nullptr,
            T_, DI_, D_, D_, D_, DI_, 1, 0,0,0,0,0,0, 0.f);

        silu_mul_kernel<<<T_*DI_/256, 256>>>(gate, up);

        gemm_kernel<128,64,16,8,4,true,EPI_RES><<<gp,256>>>(
            gate, w_down + (size_t)l*D_*DI_, h, nullptr,
            T_, D_, DI_, DI_, DI_, D_, 1, 0,0,0,0,0,0, 0.f);
    }

    rmsnorm_kernel<<<T_, 256>>>(h, norm_w, hn);

    const dim3 gl(V_/128, T_/128, 1);
    gemm_kernel<128,128,16,8,8,true,EPI_NONE><<<gl,256>>>(
        hn, emb, out, nullptr,
        T_, V_, D_, D_, D_, V_, 1, 0,0,0,0,0,0, 0.f);
}

// round 4
// speedup vs baseline: 1.6880x; 1.6880x over previous
#include <cuda_runtime.h>
#include <cuda_bf16.h>
#include <cstdint>
#include <math.h>

#define L_  8
#define D_  1024
#define H_  16
#define DH_ 64
#define DI_ 4096
#define V_  32000
#define B_  2
#define S_  1024
#define T_  (B_*S_)

// ---------------- scratch (static device arrays; no allocation) ----------------
__device__ float g_h   [T_*D_];
__device__ float g_hn  [T_*D_];
__device__ float g_q   [T_*D_];
__device__ float g_k   [T_*D_];
__device__ float g_v   [T_*D_];
__device__ float g_y   [T_*D_];
__device__ float g_gate[T_*DI_];
__device__ float g_up  [T_*DI_];
__device__ float g_att [(size_t)B_*H_*S_*S_];
__device__ float g_cos [S_*32];
__device__ float g_sin [S_*32];

// ---------------- small kernels ----------------
__global__ void embed_kernel(const int* __restrict__ x, const float* __restrict__ emb,
                             float* __restrict__ h) {
    int i = blockIdx.x * blockDim.x + threadIdx.x;
    int t = i / (D_/4);
    int c = i % (D_/4);
    float4 v = *(const float4*)(emb + (size_t)x[t]*D_ + c*4);
    *(float4*)(h + (size_t)t*D_ + c*4) = v;
}

__global__ void rope_cache_kernel() {
    int i = blockIdx.x * blockDim.x + threadIdx.x;
    if (i >= S_*32) return;
    int s = i / 32, j = i % 32;
    double inv = pow(10000.0, -(double)j / 32.0);
    double ph = (double)s * inv;
    g_cos[i] = (float)cos(ph);
    g_sin[i] = (float)sin(ph);
}

__global__ void rope_kernel(float* __restrict__ q, float* __restrict__ k) {
    int i = blockIdx.x * blockDim.x + threadIdx.x;
    int t = i >> 9;
    int r = i & 511;
    int h = r >> 5, d = r & 31;
    int s = t & (S_-1);
    float c  = g_cos[s*32 + d];
    float sn = g_sin[s*32 + d];
    size_t base = (size_t)t*D_ + h*DH_ + d;
    float a, b;
    a = q[base]; b = q[base+32];
    q[base]    = a*c - b*sn;
    q[base+32] = b*c + a*sn;
    a = k[base]; b = k[base+32];
    k[base]    = a*c - b*sn;
    k[base+32] = b*c + a*sn;
}

__global__ void rmsnorm_kernel(const float* __restrict__ x, const float* __restrict__ w,
                               float* __restrict__ o) {
    int t = blockIdx.x;
    int tid = threadIdx.x;
    const float* xp = x + (size_t)t*D_;
    float v[4];
    float s = 0.f;
    #pragma unroll
    for (int i = 0; i < 4; i++) { v[i] = xp[tid + i*256]; s += v[i]*v[i]; }
    #pragma unroll
    for (int off = 16; off; off >>= 1) s += __shfl_xor_sync(0xffffffffu, s, off);
    __shared__ float red[8];
    if ((tid & 31) == 0) red[tid >> 5] = s;
    __syncthreads();
    if (tid < 32) {
        float s2 = (tid < 8) ? red[tid] : 0.f;
        #pragma unroll
        for (int off = 4; off; off >>= 1) s2 += __shfl_xor_sync(0xffffffffu, s2, off);
        if (tid == 0) red[0] = s2;
    }
    __syncthreads();
    float r = rsqrtf(red[0] * (1.f/(float)D_) + 1e-6f);
    float* op = o + (size_t)t*D_;
    #pragma unroll
    for (int i = 0; i < 4; i++) op[tid + i*256] = w[tid + i*256] * v[i] * r;
}

__global__ void softmax_kernel(float* __restrict__ att) {
    float* p = att + (size_t)blockIdx.x * S_;
    int tid = threadIdx.x;
    float vals[4];
    float mx = -INFINITY;
    #pragma unroll
    for (int i = 0; i < 4; i++) { vals[i] = p[tid + i*256]; mx = fmaxf(mx, vals[i]); }
    #pragma unroll
    for (int off = 16; off; off >>= 1) mx = fmaxf(mx, __shfl_xor_sync(0xffffffffu, mx, off));
    __shared__ float redm[8];
    if ((tid & 31) == 0) redm[tid >> 5] = mx;
    __syncthreads();
    if (tid < 32) {
        float m2 = (tid < 8) ? redm[tid] : -INFINITY;
        #pragma unroll
        for (int off = 4; off; off >>= 1) m2 = fmaxf(m2, __shfl_xor_sync(0xffffffffu, m2, off));
        if (tid == 0) redm[0] = m2;
    }
    __syncthreads();
    float m = redm[0];
    float s = 0.f;
    #pragma unroll
    for (int i = 0; i < 4; i++) { vals[i] = expf(vals[i] - m); s += vals[i]; }
    #pragma unroll
    for (int off = 16; off; off >>= 1) s += __shfl_xor_sync(0xffffffffu, s, off);
    __shared__ float reds[8];
    if ((tid & 31) == 0) reds[tid >> 5] = s;
    __syncthreads();
    if (tid < 32) {
        float s2 = (tid < 8) ? reds[tid] : 0.f;
        #pragma unroll
        for (int off = 4; off; off >>= 1) s2 += __shfl_xor_sync(0xffffffffu, s2, off);
        if (tid == 0) reds[0] = s2;
    }
    __syncthreads();
    float inv = 1.f / reds[0];
    #pragma unroll
    for (int i = 0; i < 4; i++) p[tid + i*256] = vals[i] * inv;
}

__global__ void silu_mul_kernel(float* __restrict__ g, const float* __restrict__ u) {
    int i = blockIdx.x * blockDim.x + threadIdx.x;
    float x = g[i];
    float sg = 1.f / (1.f + expf(-x));
    g[i] = x * sg * u[i];
}

// ---------------- bf16x3 split-precision tensor-core GEMM ----------------
enum { EPI_NONE = 0, EPI_BIAS = 1, EPI_BIAS_RES = 2, EPI_RES = 3, EPI_SCORES = 4 };

__device__ __forceinline__ void mma_bf16(float* d, const uint32_t* a, const uint32_t* b) {
    asm volatile(
        "mma.sync.aligned.m16n8k16.row.col.f32.bf16.bf16.f32 "
        "{%0,%1,%2,%3}, {%4,%5,%6,%7}, {%8,%9}, {%0,%1,%2,%3};\n"
        : "+f"(d[0]), "+f"(d[1]), "+f"(d[2]), "+f"(d[3])
        : "r"(a[0]), "r"(a[1]), "r"(a[2]), "r"(a[3]),
          "r"(b[0]), "r"(b[1]));
}

// pack two floats into (hi bf16x2, lo bf16x2)
__device__ __forceinline__ void split2(float a, float b, uint32_t& hi, uint32_t& lo) {
    __nv_bfloat16 ha = __float2bfloat16(a);
    __nv_bfloat16 hb = __float2bfloat16(b);
    __nv_bfloat16 la = __float2bfloat16(a - __bfloat162float(ha));
    __nv_bfloat16 lb = __float2bfloat16(b - __bfloat162float(hb));
    hi = ((uint32_t)__bfloat16_as_ushort(hb) << 16) | __bfloat16_as_ushort(ha);
    lo = ((uint32_t)__bfloat16_as_ushort(lb) << 16) | __bfloat16_as_ushort(la);
}

// C[M,N] = A[M,K] @ op(B).  BT=true: B is [N,K] row-major. BT=false: B is [K,N] row-major.
// TRIMK: trim K loop to m0+BM (att@V causal structure).
template<int BM, int BN, int BK, int WM, int WN, bool BT, int EPI, bool TRIMK>
__global__ __launch_bounds__((BM/WM)*(BN/WN)*32)
void gemm_tc(const float* __restrict__ A, const float* __restrict__ Bm,
             float* __restrict__ C, const float* __restrict__ bias,
             int M, int N, int K, int lda, int ldb, int ldc,
             int zinner,
             long long sAo, long long sAi,
             long long sBo, long long sBi,
             long long sCo, long long sCi,
             float scale)
{
    constexpr int WARPS_N = BN/WN;
    constexpr int THREADS = (BM/WM)*(BN/WN)*32;
    constexpr int MT = WM/16;
    constexpr int NT = WN/8;
    constexpr int SP = BK/2 + 4;   // smem stride in uint32 pair units (20 for BK=32)

    const int tid = threadIdx.x;
    const int z  = blockIdx.z;
    const int zo = z / zinner, zi = z % zinner;
    const float* Ab = A  + zo*sAo + zi*sAi;
    const float* Bb = Bm + zo*sBo + zi*sBi;
    float*       Cb = C  + zo*sCo + zi*sCi;
    const int m0 = blockIdx.y * BM;
    const int n0 = blockIdx.x * BN;

    // fully masked causal block: write -inf and leave
    if (EPI == EPI_SCORES && n0 >= m0 + BM) {
        for (int f = tid; f < BM*BN/4; f += THREADS) {
            int r  = f / (BN/4);
            int c4 = f % (BN/4);
            *(float4*)(Cb + (size_t)(m0+r)*ldc + n0 + c4*4) =
                make_float4(-INFINITY, -INFINITY, -INFINITY, -INFINITY);
        }
        return;
    }

    // hi/lo bf16 pair arrays; [row][k-pair]
    __shared__ uint32_t Ah[BM][SP], Al[BM][SP];
    __shared__ uint32_t Bh[BN][SP], Bl[BN][SP];

    const int warp = tid >> 5;
    const int lane = tid & 31;
    const int g = lane >> 2;     // 0..7
    const int c = lane & 3;      // 0..3
    const int wn = warp % WARPS_N;
    const int wm = warp / WARPS_N;

    float acc[MT][NT][4];
    #pragma unroll
    for (int i = 0; i < MT; i++)
        #pragma unroll
        for (int j = 0; j < NT; j++)
            #pragma unroll
            for (int r = 0; r < 4; r++) acc[i][j][r] = 0.f;

    const int Kend = TRIMK ? min(K, m0 + BM) : K;

    for (int kt = 0; kt < Kend; kt += BK) {
        // A tile: [M,K] row-major -> pairs along k
        #pragma unroll
        for (int i = 0; i < (BM*BK/4)/THREADS; i++) {
            int f  = tid + i*THREADS;
            int r  = f / (BK/4);
            int c4 = f % (BK/4);
            float4 v = *(const float4*)(Ab + (size_t)(m0+r)*lda + kt + c4*4);
            uint32_t h0, l0, h1, l1;
            split2(v.x, v.y, h0, l0);
            split2(v.z, v.w, h1, l1);
            Ah[r][c4*2]   = h0; Ah[r][c4*2+1] = h1;
            Al[r][c4*2]   = l0; Al[r][c4*2+1] = l1;
        }
        if (BT) {
            #pragma unroll
            for (int i = 0; i < (BN*BK/4)/THREADS; i++) {
                int f  = tid + i*THREADS;
                int r  = f / (BK/4);
                int c4 = f % (BK/4);
                float4 v = *(const float4*)(Bb + (size_t)(n0+r)*ldb + kt + c4*4);
                uint32_t h0, l0, h1, l1;
                split2(v.x, v.y, h0, l0);
                split2(v.z, v.w, h1, l1);
                Bh[r][c4*2]   = h0; Bh[r][c4*2+1] = h1;
                Bl[r][c4*2]   = l0; Bl[r][c4*2+1] = l1;
            }
        } else {
            // B: [K,N] row-major, transpose into [n][k] bf16 halves.
            // RACE-FREE: each (k,n) element is an independent 16-bit store.
            #pragma unroll
            for (int i = 0; i < (BK*BN/4)/THREADS; i++) {
                int f  = tid + i*THREADS;
                int r  = f / (BN/4);      // k within tile
                int c4 = f % (BN/4);
                float4 v = *(const float4*)(Bb + (size_t)(kt+r)*ldb + n0 + c4*4);
                float vv[4] = {v.x, v.y, v.z, v.w};
                #pragma unroll
                for (int q = 0; q < 4; q++) {
                    __nv_bfloat16 hb = __float2bfloat16(vv[q]);
                    __nv_bfloat16 lb = __float2bfloat16(vv[q] - __bfloat162float(hb));
                    ((uint16_t*)Bh[c4*4+q])[r] = __bfloat16_as_ushort(hb);
                    ((uint16_t*)Bl[c4*4+q])[r] = __bfloat16_as_ushort(lb);
                }
            }
        }
        __syncthreads();

        #pragma unroll
        for (int ks = 0; ks < BK; ks += 16) {
            const int kp = ks >> 1;
            uint32_t ah[MT][4], al[MT][4], bh[NT][2], bl[NT][2];
            #pragma unroll
            for (int i = 0; i < MT; i++) {
                int mr = wm*WM + i*16 + g;
                ah[i][0] = Ah[mr  ][kp + c];   al[i][0] = Al[mr  ][kp + c];
                ah[i][1] = Ah[mr+8][kp + c];   al[i][1] = Al[mr+8][kp + c];
                ah[i][2] = Ah[mr  ][kp + c+4]; al[i][2] = Al[mr  ][kp + c+4];
                ah[i][3] = Ah[mr+8][kp + c+4]; al[i][3] = Al[mr+8][kp + c+4];
            }
            #pragma unroll
            for (int j = 0; j < NT; j++) {
                int nr = wn*WN + j*8 + g;
                bh[j][0] = Bh[nr][kp + c];   bl[j][0] = Bl[nr][kp + c];
                bh[j][1] = Bh[nr][kp + c+4]; bl[j][1] = Bl[nr][kp + c+4];
            }
            #pragma unroll
            for (int i = 0; i < MT; i++)
                #pragma unroll
                for (int j = 0; j < NT; j++) {
                    mma_bf16(acc[i][j], ah[i], bh[j]);
                    mma_bf16(acc[i][j], ah[i], bl[j]);
                    mma_bf16(acc[i][j], al[i], bh[j]);
                }
        }
        __syncthreads();
    }

    // epilogue: each thread owns rows (g, g+8) x cols (2c, 2c+1) per mma tile
    #pragma unroll
    for (int i = 0; i < MT; i++) {
        #pragma unroll
        for (int j = 0; j < NT; j++) {
            int n = n0 + wn*WN + j*8 + 2*c;
            #pragma unroll
            for (int rr = 0; rr < 2; rr++) {
                int m = m0 + wm*WM + i*16 + g + rr*8;
                float v0 = acc[i][j][rr*2 + 0];
                float v1 = acc[i][j][rr*2 + 1];
                size_t off = (size_t)m*ldc + n;
                if (EPI == EPI_BIAS)          { v0 += bias[n]; v1 += bias[n+1]; }
                else if (EPI == EPI_BIAS_RES) { v0 += bias[n]   + Cb[off];
                                                v1 += bias[n+1] + Cb[off+1]; }
                else if (EPI == EPI_RES)      { v0 += Cb[off]; v1 += Cb[off+1]; }
                else if (EPI == EPI_SCORES)   { v0 = (n   <= m) ? v0*scale : -INFINITY;
                                                v1 = (n+1 <= m) ? v1*scale : -INFINITY; }
                *(float2*)(Cb + off) = make_float2(v0, v1);
            }
        }
    }
}

// ---------------- host ----------------
extern "C" void kernel_launch(void* const* d_in, const int* in_sizes, int n_in,
                              void* d_out, int out_size) {
    const int*   x      = (const int*)  d_in[0];
    const float* emb    = (const float*)d_in[1];
    const float* wq     = (const float*)d_in[2];
    const float* bq     = (const float*)d_in[3];
    const float* wk     = (const float*)d_in[4];
    const float* bk     = (const float*)d_in[5];
    const float* wv     = (const float*)d_in[6];
    const float* bv     = (const float*)d_in[7];
    const float* wo     = (const float*)d_in[8];
    const float* bo     = (const float*)d_in[9];
    const float* w_gate = (const float*)d_in[10];
    const float* w_up   = (const float*)d_in[11];
    const float* w_down = (const float*)d_in[12];
    const float* ln1    = (const float*)d_in[13];
    const float* ln2    = (const float*)d_in[14];
    const float* norm_w = (const float*)d_in[15];
    float* out = (float*)d_out;

    float *h, *hn, *q, *k, *v, *y, *gate, *up, *att;
    cudaGetSymbolAddress((void**)&h,    g_h);
    cudaGetSymbolAddress((void**)&hn,   g_hn);
    cudaGetSymbolAddress((void**)&q,    g_q);
    cudaGetSymbolAddress((void**)&k,    g_k);
    cudaGetSymbolAddress((void**)&v,    g_v);
    cudaGetSymbolAddress((void**)&y,    g_y);
    cudaGetSymbolAddress((void**)&gate, g_gate);
    cudaGetSymbolAddress((void**)&up,   g_up);
    cudaGetSymbolAddress((void**)&att,  g_att);

    embed_kernel<<<T_*D_/4/256, 256>>>(x, emb, h);
    rope_cache_kernel<<<(S_*32 + 255)/256, 256>>>();

    const dim3 gp(D_/128,  T_/128, 1);     // proj GEMMs
    const dim3 gm(DI_/128, T_/128, 1);     // MLP GEMMs
    const dim3 gs(S_/128,  S_/128, B_*H_); // scores
    const dim3 ga(1,       S_/128, B_*H_); // attn*V

    for (int l = 0; l < L_; l++) {
        rmsnorm_kernel<<<T_, 256>>>(h, ln1 + (size_t)l*D_, hn);

        gemm_tc<128,128,32,64,32,true,EPI_BIAS,false><<<gp,256>>>(
            hn, wq + (size_t)l*D_*D_, q, bq + (size_t)l*D_,
            T_, D_, D_, D_, D_, D_, 1, 0,0,0,0,0,0, 0.f);
        gemm_tc<128,128,32,64,32,true,EPI_BIAS,false><<<gp,256>>>(
            hn, wk + (size_t)l*D_*D_, k, bk + (size_t)l*D_,
            T_, D_, D_, D_, D_, D_, 1, 0,0,0,0,0,0, 0.f);
        gemm_tc<128,128,32,64,32,true,EPI_BIAS,false><<<gp,256>>>(
            hn, wv + (size_t)l*D_*D_, v, bv + (size_t)l*D_,
            T_, D_, D_, D_, D_, D_, 1, 0,0,0,0,0,0, 0.f);

        rope_kernel<<<T_*H_*32/256, 256>>>(q, k);

        gemm_tc<128,128,32,64,32,true,EPI_SCORES,false><<<gs,256>>>(
            q, k, att, nullptr,
            S_, S_, DH_, D_, D_, S_,
            H_,
            (long long)S_*D_, (long long)DH_,
            (long long)S_*D_, (long long)DH_,
            (long long)H_*S_*S_, (long long)S_*S_,
            0.125f);

        softmax_kernel<<<B_*H_*S_, 256>>>(att);

        gemm_tc<128,64,32,32,32,false,EPI_NONE,true><<<ga,256>>>(
            att, v, y, nullptr,
            S_, DH_, S_, S_, D_, D_,
            H_,
            (long long)H_*S_*S_, (long long)S_*S_,
            (long long)S_*D_, (long long)DH_,
            (long long)S_*D_, (long long)DH_,
            0.f);

        gemm_tc<128,128,32,64,32,true,EPI_BIAS_RES,false><<<gp,256>>>(
            y, wo + (size_t)l*D_*D_, h, bo + (size_t)l*D_,
            T_, D_, D_, D_, D_, D_, 1, 0,0,0,0,0,0, 0.f);

        rmsnorm_kernel<<<T_, 256>>>(h, ln2 + (size_t)l*D_, hn);

        gemm_tc<128,128,32,64,32,true,EPI_NONE,false><<<gm,256>>>(
            hn, w_gate + (size_t)l*DI_*D_, gate, nullptr,
            T_, DI_, D_, D_, D_, DI_, 1, 0,0,0,0,0,0, 0.f);
        gemm_tc<128,128,32,64,32,true,EPI_NONE,false><<<gm,256>>>(
            hn, w_up + (size_t)l*DI_*D_, up, nullptr,
            T_, DI_, D_, D_, D_, DI_, 1, 0,0,0,0,0,0, 0.f);

        silu_mul_kernel<<<T_*DI_/256, 256>>>(gate, up);

        gemm_tc<128,128,32,64,32,true,EPI_RES,false><<<gp,256>>>(
            gate, w_down + (size_t)l*D_*DI_, h, nullptr,
            T_, D_, DI_, DI_, DI_, D_, 1, 0,0,0,0,0,0, 0.f);
    }

    rmsnorm_kernel<<<T_, 256>>>(h, norm_w, hn);

    const dim3 gl(V_/128, T_/128, 1);
    gemm_tc<128,128,32,64,32,true,EPI_NONE,false><<<gl,256>>>(
        hn, emb, out, nullptr,
        T_, V_, D_, D_, D_, V_, 1, 0,0,0,0,0,0, 0.f);
}

// round 5
// speedup vs baseline: 2.0300x; 1.2026x over previous
#include <cuda_runtime.h>
#include <cuda_bf16.h>
#include <cstdint>
#include <math.h>

#define L_  8
#define D_  1024
#define H_  16
#define DH_ 64
#define DI_ 4096
#define V_  32000
#define B_  2
#define S_  1024
#define T_  (B_*S_)

// ---------------- scratch ----------------
__device__ float g_h   [T_*D_];
__device__ float g_hn  [T_*D_];
__device__ float g_q   [T_*D_];
__device__ float g_k   [T_*D_];
__device__ float g_v   [T_*D_];
__device__ float g_y   [T_*D_];
__device__ float g_gate[T_*DI_];
__device__ float g_up  [T_*DI_];
__device__ float g_att [(size_t)B_*H_*S_*S_];
__device__ float g_cos [S_*32];
__device__ float g_sin [S_*32];

// ---------------- small kernels ----------------
__global__ void embed_kernel(const int* __restrict__ x, const float* __restrict__ emb,
                             float* __restrict__ h) {
    int i = blockIdx.x * blockDim.x + threadIdx.x;
    int t = i / (D_/4);
    int c = i % (D_/4);
    float4 v = *(const float4*)(emb + (size_t)x[t]*D_ + c*4);
    *(float4*)(h + (size_t)t*D_ + c*4) = v;
}

__global__ void rope_cache_kernel() {
    int i = blockIdx.x * blockDim.x + threadIdx.x;
    if (i >= S_*32) return;
    int s = i / 32, j = i % 32;
    double inv = pow(10000.0, -(double)j / 32.0);
    double ph = (double)s * inv;
    g_cos[i] = (float)cos(ph);
    g_sin[i] = (float)sin(ph);
}

__global__ void rope_kernel(float* __restrict__ q, float* __restrict__ k) {
    int i = blockIdx.x * blockDim.x + threadIdx.x;
    int t = i >> 9;
    int r = i & 511;
    int h = r >> 5, d = r & 31;
    int s = t & (S_-1);
    float c  = g_cos[s*32 + d];
    float sn = g_sin[s*32 + d];
    size_t base = (size_t)t*D_ + h*DH_ + d;
    float a, b;
    a = q[base]; b = q[base+32];
    q[base]    = a*c - b*sn;
    q[base+32] = b*c + a*sn;
    a = k[base]; b = k[base+32];
    k[base]    = a*c - b*sn;
    k[base+32] = b*c + a*sn;
}

__global__ void rmsnorm_kernel(const float* __restrict__ x, const float* __restrict__ w,
                               float* __restrict__ o) {
    int t = blockIdx.x;
    int tid = threadIdx.x;
    const float* xp = x + (size_t)t*D_;
    float v[4];
    float s = 0.f;
    #pragma unroll
    for (int i = 0; i < 4; i++) { v[i] = xp[tid + i*256]; s += v[i]*v[i]; }
    #pragma unroll
    for (int off = 16; off; off >>= 1) s += __shfl_xor_sync(0xffffffffu, s, off);
    __shared__ float red[8];
    if ((tid & 31) == 0) red[tid >> 5] = s;
    __syncthreads();
    if (tid < 32) {
        float s2 = (tid < 8) ? red[tid] : 0.f;
        #pragma unroll
        for (int off = 4; off; off >>= 1) s2 += __shfl_xor_sync(0xffffffffu, s2, off);
        if (tid == 0) red[0] = s2;
    }
    __syncthreads();
    float r = rsqrtf(red[0] * (1.f/(float)D_) + 1e-6f);
    float* op = o + (size_t)t*D_;
    #pragma unroll
    for (int i = 0; i < 4; i++) op[tid + i*256] = w[tid + i*256] * v[i] * r;
}

// causal softmax: masks j>row at read, writes zeros beyond row.
__global__ void softmax_kernel(float* __restrict__ att) {
    int row = blockIdx.x & (S_-1);
    float* p = att + (size_t)blockIdx.x * S_;
    int tid = threadIdx.x;
    float vals[4];
    float mx = -INFINITY;
    #pragma unroll
    for (int i = 0; i < 4; i++) {
        int j = tid + i*256;
        vals[i] = (j <= row) ? p[j] : -INFINITY;
        mx = fmaxf(mx, vals[i]);
    }
    #pragma unroll
    for (int off = 16; off; off >>= 1) mx = fmaxf(mx, __shfl_xor_sync(0xffffffffu, mx, off));
    __shared__ float redm[8];
    if ((tid & 31) == 0) redm[tid >> 5] = mx;
    __syncthreads();
    if (tid < 32) {
        float m2 = (tid < 8) ? redm[tid] : -INFINITY;
        #pragma unroll
        for (int off = 4; off; off >>= 1) m2 = fmaxf(m2, __shfl_xor_sync(0xffffffffu, m2, off));
        if (tid == 0) redm[0] = m2;
    }
    __syncthreads();
    float m = redm[0];
    float s = 0.f;
    #pragma unroll
    for (int i = 0; i < 4; i++) { vals[i] = expf(vals[i] - m); s += vals[i]; }
    #pragma unroll
    for (int off = 16; off; off >>= 1) s += __shfl_xor_sync(0xffffffffu, s, off);
    __shared__ float reds[8];
    if ((tid & 31) == 0) reds[tid >> 5] = s;
    __syncthreads();
    if (tid < 32) {
        float s2 = (tid < 8) ? reds[tid] : 0.f;
        #pragma unroll
        for (int off = 4; off; off >>= 1) s2 += __shfl_xor_sync(0xffffffffu, s2, off);
        if (tid == 0) reds[0] = s2;
    }
    __syncthreads();
    float inv = 1.f / reds[0];
    #pragma unroll
    for (int i = 0; i < 4; i++) p[tid + i*256] = vals[i] * inv;
}

// ---------------- bf16x3 split-precision tensor-core GEMM, 2-stage pipelined ----------------
enum { EPI_NONE = 0, EPI_BIAS = 1, EPI_BIAS_RES = 2, EPI_RES = 3, EPI_SCORES = 4, EPI_SILU = 5 };

__device__ __forceinline__ void mma_bf16(float* d, const uint32_t* a, const uint32_t* b) {
    asm volatile(
        "mma.sync.aligned.m16n8k16.row.col.f32.bf16.bf16.f32 "
        "{%0,%1,%2,%3}, {%4,%5,%6,%7}, {%8,%9}, {%0,%1,%2,%3};\n"
        : "+f"(d[0]), "+f"(d[1]), "+f"(d[2]), "+f"(d[3])
        : "r"(a[0]), "r"(a[1]), "r"(a[2]), "r"(a[3]),
          "r"(b[0]), "r"(b[1]));
}

__device__ __forceinline__ void split2(float a, float b, uint32_t& hi, uint32_t& lo) {
    __nv_bfloat16 ha = __float2bfloat16(a);
    __nv_bfloat16 hb = __float2bfloat16(b);
    __nv_bfloat16 la = __float2bfloat16(a - __bfloat162float(ha));
    __nv_bfloat16 lb = __float2bfloat16(b - __bfloat162float(hb));
    hi = ((uint32_t)__bfloat16_as_ushort(hb) << 16) | __bfloat16_as_ushort(ha);
    lo = ((uint32_t)__bfloat16_as_ushort(lb) << 16) | __bfloat16_as_ushort(la);
}

template<int BM, int BN, int BK, int WM, int WN, bool BT, int EPI, bool TRIMK>
__global__ __launch_bounds__((BM/WM)*(BN/WN)*32)
void gemm_tc(const float* __restrict__ A, const float* __restrict__ Bm,
             float* __restrict__ C, const float* __restrict__ bias,
             int M, int N, int K, int lda, int ldb, int ldc,
             int zinner,
             long long sAo, long long sAi,
             long long sBo, long long sBi,
             long long sCo, long long sCi,
             float scale)
{
    constexpr int WARPS_N = BN/WN;
    constexpr int THREADS = (BM/WM)*(BN/WN)*32;
    constexpr int MT = WM/16;
    constexpr int NT = WN/8;
    constexpr int SP = BK/2 + 4;            // uint32 stride per row
    constexpr int SZA = BM*SP;
    constexpr int SZB = BN*SP;
    constexpr int STAGE = 2*SZA + 2*SZB;    // Ah,Al,Bh,Bl
    constexpr int NA = (BM*BK/4)/THREADS;   // float4 per thread (A)
    constexpr int NB = BT ? (BN*BK/4)/THREADS : (BK*BN/4)/THREADS;

    extern __shared__ uint32_t smem_u[];

    const int tid = threadIdx.x;
    const int z  = blockIdx.z;
    const int zo = z / zinner, zi = z % zinner;
    const float* Ab = A  + zo*sAo + zi*sAi;
    const float* Bb = Bm + zo*sBo + zi*sBi;
    float*       Cb = C  + zo*sCo + zi*sCi;
    const int m0 = blockIdx.y * BM;
    const int n0 = blockIdx.x * BN;

    // upper-triangle causal block: nothing to do (softmax masks + zero-fills)
    if (EPI == EPI_SCORES && n0 >= m0 + BM) return;

    const int warp = tid >> 5;
    const int lane = tid & 31;
    const int g = lane >> 2;
    const int c = lane & 3;
    const int wn = warp % WARPS_N;
    const int wm = warp / WARPS_N;

    float acc[MT][NT][4];
    #pragma unroll
    for (int i = 0; i < MT; i++)
        #pragma unroll
        for (int j = 0; j < NT; j++)
            #pragma unroll
            for (int r = 0; r < 4; r++) acc[i][j][r] = 0.f;

    const int Kend = TRIMK ? min(K, m0 + BM) : K;
    const int nk = Kend / BK;

    float4 pa[NA], pb[NB];

    auto load_gmem = [&](int kt) {
        #pragma unroll
        for (int i = 0; i < NA; i++) {
            int f  = tid + i*THREADS;
            int r  = f / (BK/4);
            int c4 = f % (BK/4);
            pa[i] = *(const float4*)(Ab + (size_t)(m0+r)*lda + kt + c4*4);
        }
        if (BT) {
            #pragma unroll
            for (int i = 0; i < NB; i++) {
                int f  = tid + i*THREADS;
                int r  = f / (BK/4);
                int c4 = f % (BK/4);
                pb[i] = *(const float4*)(Bb + (size_t)(n0+r)*ldb + kt + c4*4);
            }
        } else {
            #pragma unroll
            for (int i = 0; i < NB; i++) {
                int f  = tid + i*THREADS;
                int r  = f / (BN/4);
                int c4 = f % (BN/4);
                pb[i] = *(const float4*)(Bb + (size_t)(kt+r)*ldb + n0 + c4*4);
            }
        }
    };

    auto store_split = [&](int s) {
        uint32_t* Ah = smem_u + s*STAGE;
        uint32_t* Al = Ah + SZA;
        uint32_t* Bh = Al + SZA;
        uint32_t* Bl = Bh + SZB;
        #pragma unroll
        for (int i = 0; i < NA; i++) {
            int f  = tid + i*THREADS;
            int r  = f / (BK/4);
            int c4 = f % (BK/4);
            uint32_t h0, l0, h1, l1;
            split2(pa[i].x, pa[i].y, h0, l0);
            split2(pa[i].z, pa[i].w, h1, l1);
            Ah[r*SP + c4*2]   = h0; Ah[r*SP + c4*2+1] = h1;
            Al[r*SP + c4*2]   = l0; Al[r*SP + c4*2+1] = l1;
        }
        if (BT) {
            #pragma unroll
            for (int i = 0; i < NB; i++) {
                int f  = tid + i*THREADS;
                int r  = f / (BK/4);
                int c4 = f % (BK/4);
                uint32_t h0, l0, h1, l1;
                split2(pb[i].x, pb[i].y, h0, l0);
                split2(pb[i].z, pb[i].w, h1, l1);
                Bh[r*SP + c4*2]   = h0; Bh[r*SP + c4*2+1] = h1;
                Bl[r*SP + c4*2]   = l0; Bl[r*SP + c4*2+1] = l1;
            }
        } else {
            // transpose path: independent 16-bit stores (race-free)
            #pragma unroll
            for (int i = 0; i < NB; i++) {
                int f  = tid + i*THREADS;
                int r  = f / (BN/4);      // k within tile
                int c4 = f % (BN/4);
                float vv[4] = {pb[i].x, pb[i].y, pb[i].z, pb[i].w};
                #pragma unroll
                for (int q = 0; q < 4; q++) {
                    __nv_bfloat16 hb = __float2bfloat16(vv[q]);
                    __nv_bfloat16 lb = __float2bfloat16(vv[q] - __bfloat162float(hb));
                    ((uint16_t*)(Bh + (c4*4+q)*SP))[r] = __bfloat16_as_ushort(hb);
                    ((uint16_t*)(Bl + (c4*4+q)*SP))[r] = __bfloat16_as_ushort(lb);
                }
            }
        }
    };

    load_gmem(0);
    store_split(0);
    __syncthreads();

    for (int t = 0; t < nk; t++) {
        const int cur = t & 1;
        if (t + 1 < nk) load_gmem((t+1)*BK);   // issue gmem loads early

        const uint32_t* Ah = smem_u + cur*STAGE;
        const uint32_t* Al = Ah + SZA;
        const uint32_t* Bh = Al + SZA;
        const uint32_t* Bl = Bh + SZB;

        #pragma unroll
        for (int ks = 0; ks < BK; ks += 16) {
            const int kp = ks >> 1;
            uint32_t ah[MT][4], al[MT][4], bh[NT][2], bl[NT][2];
            #pragma unroll
            for (int i = 0; i < MT; i++) {
                int mr = wm*WM + i*16 + g;
                ah[i][0] = Ah[mr*SP     + kp + c];   al[i][0] = Al[mr*SP     + kp + c];
                ah[i][1] = Ah[(mr+8)*SP + kp + c];   al[i][1] = Al[(mr+8)*SP + kp + c];
                ah[i][2] = Ah[mr*SP     + kp + c+4]; al[i][2] = Al[mr*SP     + kp + c+4];
                ah[i][3] = Ah[(mr+8)*SP + kp + c+4]; al[i][3] = Al[(mr+8)*SP + kp + c+4];
            }
            #pragma unroll
            for (int j = 0; j < NT; j++) {
                int nr = wn*WN + j*8 + g;
                bh[j][0] = Bh[nr*SP + kp + c];   bl[j][0] = Bl[nr*SP + kp + c];
                bh[j][1] = Bh[nr*SP + kp + c+4]; bl[j][1] = Bl[nr*SP + kp + c+4];
            }
            #pragma unroll
            for (int i = 0; i < MT; i++)
                #pragma unroll
                for (int j = 0; j < NT; j++) {
                    mma_bf16(acc[i][j], ah[i], bh[j]);
                    mma_bf16(acc[i][j], ah[i], bl[j]);
                    mma_bf16(acc[i][j], al[i], bh[j]);
                }
        }

        if (t + 1 < nk) store_split(cur ^ 1);
        __syncthreads();
    }

    #pragma unroll
    for (int i = 0; i < MT; i++) {
        #pragma unroll
        for (int j = 0; j < NT; j++) {
            int n = n0 + wn*WN + j*8 + 2*c;
            #pragma unroll
            for (int rr = 0; rr < 2; rr++) {
                int m = m0 + wm*WM + i*16 + g + rr*8;
                float v0 = acc[i][j][rr*2 + 0];
                float v1 = acc[i][j][rr*2 + 1];
                size_t off = (size_t)m*ldc + n;
                if (EPI == EPI_BIAS)          { v0 += bias[n]; v1 += bias[n+1]; }
                else if (EPI == EPI_BIAS_RES) { v0 += bias[n]   + Cb[off];
                                                v1 += bias[n+1] + Cb[off+1]; }
                else if (EPI == EPI_RES)      { v0 += Cb[off]; v1 += Cb[off+1]; }
                else if (EPI == EPI_SCORES)   { v0 *= scale; v1 *= scale; }
                else if (EPI == EPI_SILU)     {
                    float g0 = Cb[off], g1 = Cb[off+1];
                    v0 *= g0 / (1.f + expf(-g0));
                    v1 *= g1 / (1.f + expf(-g1));
                }
                *(float2*)(Cb + off) = make_float2(v0, v1);
            }
        }
    }
}

// ---------------- host ----------------
template<int BM, int BN, int BK>
constexpr int smem_bytes() {
    return 2 * (2*BM*(BK/2+4) + 2*BN*(BK/2+4)) * 4;
}

extern "C" void kernel_launch(void* const* d_in, const int* in_sizes, int n_in,
                              void* d_out, int out_size) {
    const int*   x      = (const int*)  d_in[0];
    const float* emb    = (const float*)d_in[1];
    const float* wq     = (const float*)d_in[2];
    const float* bq     = (const float*)d_in[3];
    const float* wk     = (const float*)d_in[4];
    const float* bk     = (const float*)d_in[5];
    const float* wv     = (const float*)d_in[6];
    const float* bv     = (const float*)d_in[7];
    const float* wo     = (const float*)d_in[8];
    const float* bo     = (const float*)d_in[9];
    const float* w_gate = (const float*)d_in[10];
    const float* w_up   = (const float*)d_in[11];
    const float* w_down = (const float*)d_in[12];
    const float* ln1    = (const float*)d_in[13];
    const float* ln2    = (const float*)d_in[14];
    const float* norm_w = (const float*)d_in[15];
    float* out = (float*)d_out;

    float *h, *hn, *q, *k, *v, *y, *gate, *up, *att;
    cudaGetSymbolAddress((void**)&h,    g_h);
    cudaGetSymbolAddress((void**)&hn,   g_hn);
    cudaGetSymbolAddress((void**)&q,    g_q);
    cudaGetSymbolAddress((void**)&k,    g_k);
    cudaGetSymbolAddress((void**)&v,    g_v);
    cudaGetSymbolAddress((void**)&y,    g_y);
    cudaGetSymbolAddress((void**)&gate, g_gate);
    cudaGetSymbolAddress((void**)&up,   g_up);
    cudaGetSymbolAddress((void**)&att,  g_att);

    constexpr int SM_P = smem_bytes<128,64,32>();    // 61440
    constexpr int SM_M = smem_bytes<128,128,32>();   // 81920

    // opt-in to >48KB dynamic smem (host-side attribute set; idempotent)
    cudaFuncSetAttribute(gemm_tc<128,64,32,32,32,true,EPI_BIAS,false>,     cudaFuncAttributeMaxDynamicSharedMemorySize, SM_P);
    cudaFuncSetAttribute(gemm_tc<128,128,32,64,32,true,EPI_SCORES,false>,  cudaFuncAttributeMaxDynamicSharedMemorySize, SM_M);
    cudaFuncSetAttribute(gemm_tc<128,64,32,32,32,false,EPI_NONE,true>,     cudaFuncAttributeMaxDynamicSharedMemorySize, SM_P);
    cudaFuncSetAttribute(gemm_tc<128,64,32,32,32,true,EPI_BIAS_RES,false>, cudaFuncAttributeMaxDynamicSharedMemorySize, SM_P);
    cudaFuncSetAttribute(gemm_tc<128,128,32,64,32,true,EPI_NONE,false>,    cudaFuncAttributeMaxDynamicSharedMemorySize, SM_M);
    cudaFuncSetAttribute(gemm_tc<128,128,32,64,32,true,EPI_SILU,false>,    cudaFuncAttributeMaxDynamicSharedMemorySize, SM_M);
    cudaFuncSetAttribute(gemm_tc<128,64,32,32,32,true,EPI_RES,false>,      cudaFuncAttributeMaxDynamicSharedMemorySize, SM_P);

    embed_kernel<<<T_*D_/4/256, 256>>>(x, emb, h);
    rope_cache_kernel<<<(S_*32 + 255)/256, 256>>>();

    const dim3 gp(D_/64,   T_/128, 1);     // proj GEMMs: 256 blocks
    const dim3 gm(DI_/128, T_/128, 1);     // MLP GEMMs: 512 blocks
    const dim3 gs(S_/128,  S_/128, B_*H_); // scores
    const dim3 ga(1,       S_/128, B_*H_); // attn*V

    for (int l = 0; l < L_; l++) {
        rmsnorm_kernel<<<T_, 256>>>(h, ln1 + (size_t)l*D_, hn);

        gemm_tc<128,64,32,32,32,true,EPI_BIAS,false><<<gp,256,SM_P>>>(
            hn, wq + (size_t)l*D_*D_, q, bq + (size_t)l*D_,
            T_, D_, D_, D_, D_, D_, 1, 0,0,0,0,0,0, 0.f);
        gemm_tc<128,64,32,32,32,true,EPI_BIAS,false><<<gp,256,SM_P>>>(
            hn, wk + (size_t)l*D_*D_, k, bk + (size_t)l*D_,
            T_, D_, D_, D_, D_, D_, 1, 0,0,0,0,0,0, 0.f);
        gemm_tc<128,64,32,32,32,true,EPI_BIAS,false><<<gp,256,SM_P>>>(
            hn, wv + (size_t)l*D_*D_, v, bv + (size_t)l*D_,
            T_, D_, D_, D_, D_, D_, 1, 0,0,0,0,0,0, 0.f);

        rope_kernel<<<T_*H_*32/256, 256>>>(q, k);

        gemm_tc<128,128,32,64,32,true,EPI_SCORES,false><<<gs,256,SM_M>>>(
            q, k, att, nullptr,
            S_, S_, DH_, D_, D_, S_,
            H_,
            (long long)S_*D_, (long long)DH_,
            (long long)S_*D_, (long long)DH_,
            (long long)H_*S_*S_, (long long)S_*S_,
            0.125f);

        softmax_kernel<<<B_*H_*S_, 256>>>(att);

        gemm_tc<128,64,32,32,32,false,EPI_NONE,true><<<ga,256,SM_P>>>(
            att, v, y, nullptr,
            S_, DH_, S_, S_, D_, D_,
            H_,
            (long long)H_*S_*S_, (long long)S_*S_,
            (long long)S_*D_, (long long)DH_,
            (long long)S_*D_, (long long)DH_,
            0.f);

        gemm_tc<128,64,32,32,32,true,EPI_BIAS_RES,false><<<gp,256,SM_P>>>(
            y, wo + (size_t)l*D_*D_, h, bo + (size_t)l*D_,
            T_, D_, D_, D_, D_, D_, 1, 0,0,0,0,0,0, 0.f);

        rmsnorm_kernel<<<T_, 256>>>(h, ln2 + (size_t)l*D_, hn);

        gemm_tc<128,128,32,64,32,true,EPI_NONE,false><<<gm,256,SM_M>>>(
            hn, w_gate + (size_t)l*DI_*D_, gate, nullptr,
            T_, DI_, D_, D_, D_, DI_, 1, 0,0,0,0,0,0, 0.f);
        // up-proj with fused silu(gate)*up, written into gate buffer
        gemm_tc<128,128,32,64,32,true,EPI_SILU,false><<<gm,256,SM_M>>>(
            hn, w_up + (size_t)l*DI_*D_, gate, nullptr,
            T_, DI_, D_, D_, D_, DI_, 1, 0,0,0,0,0,0, 0.f);

        gemm_tc<128,64,32,32,32,true,EPI_RES,false><<<gp,256,SM_P>>>(
            gate, w_down + (size_t)l*D_*DI_, h, nullptr,
            T_, D_, DI_, DI_, DI_, D_, 1, 0,0,0,0,0,0, 0.f);
    }

    rmsnorm_kernel<<<T_, 256>>>(h, norm_w, hn);

    const dim3 gl(V_/128, T_/128, 1);
    gemm_tc<128,128,32,64,32,true,EPI_NONE,false><<<gl,256,SM_M>>>(
        hn, emb, out, nullptr,
        T_, V_, D_, D_, D_, V_, 1, 0,0,0,0,0,0, 0.f);
}